// round 5
// baseline (speedup 1.0000x reference)
#include <cuda_runtime.h>
#include <cuda_bf16.h>
#include <math.h>

// ---------------------------------------------------------------------------
// Problem constants
// ---------------------------------------------------------------------------
#define BATCH    32
#define SEQ_T    257                 // 1 CLS + 256 patches
#define ROWS_T   (BATCH * SEQ_T)     // 8224
#define EMBED_D  1024
#define NBLK     12
#define NHEAD    16
#define HDIM     64
#define QKV_D    3072
#define HID_D    2816
#define PATCH_M  (BATCH * 256)       // 8192
#define PATCH_K  768

#define WQKV_SZ  ((size_t)NBLK * EMBED_D * QKV_D)
#define WO_SZ    ((size_t)NBLK * EMBED_D * EMBED_D)
#define W1_SZ    ((size_t)NBLK * EMBED_D * HID_D)
#define W2_SZ    ((size_t)NBLK * HID_D * EMBED_D)
#define W3_SZ    W1_SZ

// ---------------------------------------------------------------------------
// Scratch (static __device__ arrays; allocation is forbidden)
// ---------------------------------------------------------------------------
__device__ float g_a[(size_t)ROWS_T * EMBED_D];      // normed activations (tf32-rounded)
__device__ float g_qkv[(size_t)ROWS_T * QKV_D];      // qkv projections
__device__ float g_o[(size_t)ROWS_T * EMBED_D];      // attention output (tf32-rounded)
__device__ float g_gate[(size_t)ROWS_T * HID_D];     // w1 out, then silu*w3 (tf32-rounded)
__device__ float g_cond[(size_t)BATCH * EMBED_D];    // cond embedding
__device__ float g_fc[SEQ_T * 32 * 2];               // rope cos/sin
// tf32-rounded weight copies (one conversion pass per launch)
__device__ float g_wt[WQKV_SZ + WO_SZ + W1_SZ + W2_SZ + W3_SZ];

// ---------------------------------------------------------------------------
// TF32 helpers
// ---------------------------------------------------------------------------
__device__ __forceinline__ float f2tf32(float f) {
    unsigned u;
    asm("cvt.rna.tf32.f32 %0, %1;" : "=r"(u) : "f"(f));
    return __uint_as_float(u);
}

__device__ __forceinline__ void mma_tf32(float* c, const unsigned* a,
                                         const unsigned* b) {
    asm volatile(
        "mma.sync.aligned.m16n8k8.row.col.f32.tf32.tf32.f32 "
        "{%0,%1,%2,%3}, {%4,%5,%6,%7}, {%8,%9}, {%0,%1,%2,%3};\n"
        : "+f"(c[0]), "+f"(c[1]), "+f"(c[2]), "+f"(c[3])
        : "r"(a[0]), "r"(a[1]), "r"(a[2]), "r"(a[3]), "r"(b[0]), "r"(b[1]));
}

__device__ __forceinline__ void cp16(unsigned dst, const void* src, int sz) {
    asm volatile("cp.async.cg.shared.global [%0], [%1], 16, %2;"
                 :: "r"(dst), "l"(src), "r"(sz));
}
__device__ __forceinline__ void cp_commit() {
    asm volatile("cp.async.commit_group;" ::: "memory");
}
__device__ __forceinline__ void cp_wait0() {
    asm volatile("cp.async.wait_group 0;" ::: "memory");
}

// ---------------------------------------------------------------------------
// Weight tf32-rounding pass (float4 streaming)
// ---------------------------------------------------------------------------
__global__ void __launch_bounds__(256)
cvt_kernel(const float4* __restrict__ src, float4* __restrict__ dst, int n4) {
    int i = blockIdx.x * 256 + threadIdx.x;
    if (i < n4) {
        float4 v = src[i];
        v.x = f2tf32(v.x); v.y = f2tf32(v.y);
        v.z = f2tf32(v.z); v.w = f2tf32(v.w);
        dst[i] = v;
    }
}

// ---------------------------------------------------------------------------
// Block reduction (256 threads)
// ---------------------------------------------------------------------------
__device__ __forceinline__ float block_reduce_sum(float v) {
    __shared__ float sh[8];
    int lane = threadIdx.x & 31;
    int w = threadIdx.x >> 5;
#pragma unroll
    for (int o = 16; o; o >>= 1) v += __shfl_xor_sync(0xffffffffu, v, o);
    if (lane == 0) sh[w] = v;
    __syncthreads();
    if (w == 0) {
        v = (lane < 8) ? sh[lane] : 0.f;
#pragma unroll
        for (int o = 4; o; o >>= 1) v += __shfl_xor_sync(0xffffffffu, v, o);
        if (lane == 0) sh[0] = v;
    }
    __syncthreads();
    float r = sh[0];
    __syncthreads();
    return r;
}

// ---------------------------------------------------------------------------
// RoPE table:  fc[s][j][0]=cos, [1]=sin ; row 0 (CLS) is zeros (matches ref)
// ---------------------------------------------------------------------------
__global__ void freqs_kernel(float* __restrict__ fc) {
    int s = blockIdx.x;          // 0..256
    int j = threadIdx.x;         // 0..31
    float c = 0.f, sn = 0.f;
    if (s > 0) {
        int p = s - 1;
        int y = p >> 4, x = p & 15;
        int i = (j < 16) ? j : (j - 16);
        int t = (j < 16) ? y : x;
        float fr = powf(10000.0f, -(2.0f * (float)i) / 32.0f);
        float ang = (float)t * fr;
        c = cosf(ang);
        sn = sinf(ang);
    }
    fc[(s * 32 + j) * 2 + 0] = c;
    fc[(s * 32 + j) * 2 + 1] = sn;
}

// ---------------------------------------------------------------------------
// Pipelined TF32 GEMM: C[M,N] = A[M,K] @ B[K,N]  (epilogue per MODE)
// MODE 0: store   1: +bias   2: += C (residual)   3: silu(C)*acc, tf32-round
// CVT: round fragments at use (for raw-fp32 inputs, patch/cond GEMMs only)
// BM=BN=128, BK=32, 256 threads (8 warps, 2x4 of 64x32 warp tiles),
// 2-stage cp.async pipeline. N%128==0, K%32==0; M guarded.
// ---------------------------------------------------------------------------
#define A_ST 36                       // floats per A-row in smem
#define B_ST 132                      // floats per B-row in smem
#define ASZ (128 * A_ST)              // 4608 floats
#define BSZ (32 * B_ST)               // 4224 floats
#define STAGE_F (ASZ + BSZ)           // 8832 floats per stage
#define GEMM_SMEM (2 * STAGE_F * 4)   // 70656 bytes

template <int MODE, bool CVT>
__global__ void __launch_bounds__(256)
mma_gemm(const float* __restrict__ A, const float* __restrict__ B,
         const float* __restrict__ bias, float* __restrict__ C,
         int M, int N, int K) {
    extern __shared__ float sm[];

    const int tid = threadIdx.x;
    const int lane = tid & 31;
    const int warp = tid >> 5;
    const int gid = lane >> 2;     // 0..7
    const int ctg = lane & 3;      // 0..3
    const int mw = (warp & 1) * 64;
    const int nw = (warp >> 1) * 32;

    const int rowBase = blockIdx.y * 128;
    const int colBase = blockIdx.x * 128;

    // cp.async load mapping
    const int aF = tid & 7;        // col4 within A row (8 float4 per row)
    const int aR0 = tid >> 3;      // 0..31 (rows aR0 + 32*i)
    const int bC = tid & 31;       // col4 within B row (32 float4 per row)
    const int bR0 = tid >> 5;      // 0..7  (rows bR0 + 8*i)

    unsigned sbase;
    asm("{ .reg .u64 t; cvta.to.shared.u64 t, %1; cvt.u32.u64 %0, t; }"
        : "=r"(sbase) : "l"(sm));

    float acc[4][4][4] = {};   // [mi][ni][frag]

    auto load_stage = [&](int stage, int k0) {
        unsigned abase = sbase + (unsigned)(stage * STAGE_F) * 4u;
#pragma unroll
        for (int i = 0; i < 4; i++) {
            int r = aR0 + 32 * i;
            bool v = (rowBase + r) < M;
            const float* src = A + (size_t)(rowBase + (v ? r : 0)) * K + k0 + aF * 4;
            cp16(abase + (unsigned)(r * A_ST + aF * 4) * 4u, src, v ? 16 : 0);
        }
        unsigned bbase = abase + (unsigned)ASZ * 4u;
#pragma unroll
        for (int i = 0; i < 4; i++) {
            int r = bR0 + 8 * i;
            const float* src = B + (size_t)(k0 + r) * N + colBase + bC * 4;
            cp16(bbase + (unsigned)(r * B_ST + bC * 4) * 4u, src, 16);
        }
        cp_commit();
    };

    // prologue
    load_stage(0, 0);

    int stage = 0;
    for (int k0 = 0; k0 < K; k0 += 32, stage ^= 1) {
        cp_wait0();
        __syncthreads();
        if (k0 + 32 < K) load_stage(stage ^ 1, k0 + 32);

        const float* As = sm + stage * STAGE_F;
        const float* Bs = As + ASZ;

#pragma unroll
        for (int ks = 0; ks < 32; ks += 8) {
            unsigned af[4][4], bf[4][2];
#pragma unroll
            for (int mi = 0; mi < 4; mi++) {
                const int r0 = (mw + mi * 16 + gid) * A_ST;
                const int r8 = r0 + 8 * A_ST;
                if (CVT) {
                    af[mi][0] = __float_as_uint(f2tf32(As[r0 + ks + ctg]));
                    af[mi][1] = __float_as_uint(f2tf32(As[r8 + ks + ctg]));
                    af[mi][2] = __float_as_uint(f2tf32(As[r0 + ks + ctg + 4]));
                    af[mi][3] = __float_as_uint(f2tf32(As[r8 + ks + ctg + 4]));
                } else {
                    af[mi][0] = __float_as_uint(As[r0 + ks + ctg]);
                    af[mi][1] = __float_as_uint(As[r8 + ks + ctg]);
                    af[mi][2] = __float_as_uint(As[r0 + ks + ctg + 4]);
                    af[mi][3] = __float_as_uint(As[r8 + ks + ctg + 4]);
                }
            }
#pragma unroll
            for (int ni = 0; ni < 4; ni++) {
                const float* bp = Bs + (ks + ctg) * B_ST + nw + ni * 8 + gid;
                if (CVT) {
                    bf[ni][0] = __float_as_uint(f2tf32(bp[0]));
                    bf[ni][1] = __float_as_uint(f2tf32(bp[4 * B_ST]));
                } else {
                    bf[ni][0] = __float_as_uint(bp[0]);
                    bf[ni][1] = __float_as_uint(bp[4 * B_ST]);
                }
            }
#pragma unroll
            for (int mi = 0; mi < 4; mi++)
#pragma unroll
                for (int ni = 0; ni < 4; ni++)
                    mma_tf32(acc[mi][ni], af[mi], bf[ni]);
        }
        __syncthreads();
    }

    // epilogue
#pragma unroll
    for (int mi = 0; mi < 4; mi++) {
#pragma unroll
        for (int half = 0; half < 2; half++) {
            int row = rowBase + mw + mi * 16 + gid + half * 8;
            if (row >= M) continue;
#pragma unroll
            for (int ni = 0; ni < 4; ni++) {
                int col = colBase + nw + ni * 8 + 2 * ctg;
                float v0 = acc[mi][ni][half * 2 + 0];
                float v1 = acc[mi][ni][half * 2 + 1];
                float* Cp = C + (size_t)row * N + col;
                if (MODE == 1) {
                    v0 += bias[col];
                    v1 += bias[col + 1];
                } else if (MODE == 2) {
                    float2 old = *(const float2*)Cp;
                    v0 += old.x;
                    v1 += old.y;
                } else if (MODE == 3) {
                    float2 g = *(const float2*)Cp;
                    v0 = f2tf32(v0 * (g.x / (1.0f + __expf(-g.x))));
                    v1 = f2tf32(v1 * (g.y / (1.0f + __expf(-g.y))));
                }
                float2 out;
                out.x = v0;
                out.y = v1;
                *(float2*)Cp = out;
            }
        }
    }
}

// ---------------------------------------------------------------------------
// Embed combine (+pos) + LayerNorm -> h (d_out). One block per row.
// ---------------------------------------------------------------------------
__global__ void __launch_bounds__(256)
embed_ln_kernel(const float* __restrict__ patch, const float* __restrict__ cond,
                const float* __restrict__ pos, const float* __restrict__ g,
                const float* __restrict__ bta, float* __restrict__ h) {
    int row = blockIdx.x;
    int b = row / SEQ_T, s = row % SEQ_T;
    const float* src = (s == 0) ? (cond + (size_t)b * EMBED_D)
                                : (patch + ((size_t)b * 256 + (s - 1)) * EMBED_D);
    const float* pp = pos + (size_t)s * EMBED_D;

    float v[4];
    float sum = 0.f, sumsq = 0.f;
#pragma unroll
    for (int t = 0; t < 4; t++) {
        int idx = threadIdx.x + t * 256;
        float x = src[idx] + pp[idx];
        v[t] = x;
        sum += x;
        sumsq += x * x;
    }
    sum = block_reduce_sum(sum);
    sumsq = block_reduce_sum(sumsq);
    float mean = sum * (1.0f / EMBED_D);
    float var = sumsq * (1.0f / EMBED_D) - mean * mean;
    float inv = rsqrtf(var + 1e-6f);
#pragma unroll
    for (int t = 0; t < 4; t++) {
        int idx = threadIdx.x + t * 256;
        h[(size_t)row * EMBED_D + idx] = (v[t] - mean) * inv * g[idx] + bta[idx];
    }
}

// ---------------------------------------------------------------------------
// RMSNorm: out = tf32(x * rsqrt(mean(x^2)+eps) * w). One block per row.
// (output feeds GEMM A operands — pre-rounded)
// ---------------------------------------------------------------------------
__global__ void __launch_bounds__(256)
rmsnorm_kernel(const float* __restrict__ x, const float* __restrict__ w,
               float* __restrict__ out) {
    int row = blockIdx.x;
    const float* xp = x + (size_t)row * EMBED_D;
    float v[4];
    float ss = 0.f;
#pragma unroll
    for (int t = 0; t < 4; t++) {
        int idx = threadIdx.x + t * 256;
        v[t] = xp[idx];
        ss += v[t] * v[t];
    }
    ss = block_reduce_sum(ss);
    float inv = rsqrtf(ss * (1.0f / EMBED_D) + 1e-5f);
#pragma unroll
    for (int t = 0; t < 4; t++) {
        int idx = threadIdx.x + t * 256;
        out[(size_t)row * EMBED_D + idx] = f2tf32(v[t] * inv * w[idx]);
    }
}

// ---------------------------------------------------------------------------
// Flash attention (fp32), RoPE fused into Q/K tile loads.
// grid (qtile=5, head=16, batch=32), 256 threads, 64x64 tiles.
// Output rounded to tf32 (feeds wo GEMM).
// ---------------------------------------------------------------------------
#define ATTN_SMEM (4 * 64 * 65 * 4)

__global__ void __launch_bounds__(256)
attn_kernel(const float* __restrict__ qkv, const float* __restrict__ fc,
            float* __restrict__ o) {
    extern __shared__ float sm[];
    float* Qs = sm;                 // [64][65]
    float* Ks = sm + 64 * 65;
    float* Vs = sm + 2 * 64 * 65;
    float* Ps = sm + 3 * 64 * 65;

    const int qt = blockIdx.x;
    const int hh = blockIdx.y;
    const int bb = blockIdx.z;
    const int tid = threadIdx.x;
    const int tx = tid & 15, ty = tid >> 4;
    const int lr = tid >> 4;         // 0..15
    const int ld = (tid & 15) << 2;  // 0..60

    const size_t bhBase = (size_t)bb * SEQ_T * QKV_D + (size_t)hh * HDIM;

#pragma unroll
    for (int i = 0; i < 4; i++) {
        int r = lr + 16 * i;
        int gq = qt * 64 + r;
        float q0 = 0, q1 = 0, q2 = 0, q3 = 0;
        if (gq < SEQ_T) {
            float4 v = *(const float4*)(qkv + bhBase + (size_t)gq * QKV_D + ld);
            int j0 = ld >> 1;
            float c0 = fc[(gq * 32 + j0) * 2 + 0], s0 = fc[(gq * 32 + j0) * 2 + 1];
            float c1 = fc[(gq * 32 + j0 + 1) * 2 + 0], s1 = fc[(gq * 32 + j0 + 1) * 2 + 1];
            q0 = v.x * c0 - v.y * s0;
            q1 = v.y * c0 + v.x * s0;
            q2 = v.z * c1 - v.w * s1;
            q3 = v.w * c1 + v.z * s1;
        }
        Qs[r * 65 + ld + 0] = q0;
        Qs[r * 65 + ld + 1] = q1;
        Qs[r * 65 + ld + 2] = q2;
        Qs[r * 65 + ld + 3] = q3;
    }

    float oacc[4][4] = {};
    float m[4], l[4];
#pragma unroll
    for (int i = 0; i < 4; i++) { m[i] = -1e30f; l[i] = 0.f; }

    const int nkt = qt + 1;
    for (int kt = 0; kt < nkt; kt++) {
#pragma unroll
        for (int i = 0; i < 4; i++) {
            int r = lr + 16 * i;
            int gk = kt * 64 + r;
            float k0 = 0, k1 = 0, k2 = 0, k3 = 0, v0 = 0, v1 = 0, v2 = 0, v3 = 0;
            if (gk < SEQ_T) {
                float4 kv = *(const float4*)(qkv + bhBase + (size_t)gk * QKV_D + 1024 + ld);
                float4 vv = *(const float4*)(qkv + bhBase + (size_t)gk * QKV_D + 2048 + ld);
                int j0 = ld >> 1;
                float c0 = fc[(gk * 32 + j0) * 2 + 0], s0 = fc[(gk * 32 + j0) * 2 + 1];
                float c1 = fc[(gk * 32 + j0 + 1) * 2 + 0], s1 = fc[(gk * 32 + j0 + 1) * 2 + 1];
                k0 = kv.x * c0 - kv.y * s0;
                k1 = kv.y * c0 + kv.x * s0;
                k2 = kv.z * c1 - kv.w * s1;
                k3 = kv.w * c1 + kv.z * s1;
                v0 = vv.x; v1 = vv.y; v2 = vv.z; v3 = vv.w;
            }
            Ks[r * 65 + ld + 0] = k0;
            Ks[r * 65 + ld + 1] = k1;
            Ks[r * 65 + ld + 2] = k2;
            Ks[r * 65 + ld + 3] = k3;
            Vs[r * 65 + ld + 0] = v0;
            Vs[r * 65 + ld + 1] = v1;
            Vs[r * 65 + ld + 2] = v2;
            Vs[r * 65 + ld + 3] = v3;
        }
        __syncthreads();

        float s[4][4] = {};
#pragma unroll 4
        for (int d = 0; d < 64; d++) {
            float ra[4], rb[4];
#pragma unroll
            for (int i = 0; i < 4; i++) ra[i] = Qs[(ty * 4 + i) * 65 + d];
#pragma unroll
            for (int j = 0; j < 4; j++) rb[j] = Ks[(tx * 4 + j) * 65 + d];
#pragma unroll
            for (int i = 0; i < 4; i++)
#pragma unroll
                for (int j = 0; j < 4; j++) s[i][j] += ra[i] * rb[j];
        }

#pragma unroll
        for (int i = 0; i < 4; i++) {
            int gq = qt * 64 + ty * 4 + i;
            float rm = -1e30f;
#pragma unroll
            for (int j = 0; j < 4; j++) {
                int gk = kt * 64 + tx * 4 + j;
                float sv = s[i][j] * 0.125f;
                if (gk > gq || gk >= SEQ_T) sv = -1e30f;
                s[i][j] = sv;
                rm = fmaxf(rm, sv);
            }
#pragma unroll
            for (int off = 8; off; off >>= 1)
                rm = fmaxf(rm, __shfl_xor_sync(0xffffffffu, rm, off));
            float newm = fmaxf(m[i], rm);
            float corr = __expf(m[i] - newm);
            float rs = 0.f;
#pragma unroll
            for (int j = 0; j < 4; j++) {
                float p = __expf(s[i][j] - newm);
                s[i][j] = p;
                rs += p;
            }
#pragma unroll
            for (int off = 8; off; off >>= 1)
                rs += __shfl_xor_sync(0xffffffffu, rs, off);
            l[i] = l[i] * corr + rs;
            m[i] = newm;
#pragma unroll
            for (int j = 0; j < 4; j++) oacc[i][j] *= corr;
        }

#pragma unroll
        for (int i = 0; i < 4; i++)
#pragma unroll
            for (int j = 0; j < 4; j++)
                Ps[(ty * 4 + i) * 65 + tx * 4 + j] = s[i][j];
        __syncthreads();

#pragma unroll 4
        for (int d = 0; d < 64; d++) {
            float ra[4], rb[4];
#pragma unroll
            for (int i = 0; i < 4; i++) ra[i] = Ps[(ty * 4 + i) * 65 + d];
#pragma unroll
            for (int j = 0; j < 4; j++) rb[j] = Vs[d * 65 + tx * 4 + j];
#pragma unroll
            for (int i = 0; i < 4; i++)
#pragma unroll
                for (int j = 0; j < 4; j++) oacc[i][j] += ra[i] * rb[j];
        }
        __syncthreads();
    }

#pragma unroll
    for (int i = 0; i < 4; i++) {
        int gq = qt * 64 + ty * 4 + i;
        if (gq >= SEQ_T) continue;
        float inv = 1.0f / l[i];
        float* op = o + ((size_t)bb * SEQ_T + gq) * EMBED_D + hh * HDIM + tx * 4;
        float4 r;
        r.x = f2tf32(oacc[i][0] * inv);
        r.y = f2tf32(oacc[i][1] * inv);
        r.z = f2tf32(oacc[i][2] * inv);
        r.w = f2tf32(oacc[i][3] * inv);
        *(float4*)op = r;
    }
}

// ---------------------------------------------------------------------------
// Launcher
// ---------------------------------------------------------------------------
extern "C" void kernel_launch(void* const* d_in, const int* in_sizes, int n_in,
                              void* d_out, int out_size) {
    const float* x       = (const float*)d_in[0];
    const float* cond    = (const float*)d_in[1];
    const float* patch_w = (const float*)d_in[2];
    const float* patch_b = (const float*)d_in[3];
    const float* ln_g    = (const float*)d_in[4];
    const float* ln_b    = (const float*)d_in[5];
    const float* pos     = (const float*)d_in[6];
    const float* cond_w  = (const float*)d_in[7];
    const float* cond_b  = (const float*)d_in[8];
    const float* wqkv    = (const float*)d_in[9];
    const float* wo      = (const float*)d_in[10];
    const float* w1      = (const float*)d_in[11];
    const float* w2      = (const float*)d_in[12];
    const float* w3      = (const float*)d_in[13];
    const float* anw     = (const float*)d_in[14];
    const float* fnw     = (const float*)d_in[15];

    float* h = (float*)d_out;

    float *a, *qkvb, *ob, *gate, *condb, *fc, *wt;
    cudaGetSymbolAddress((void**)&a, g_a);
    cudaGetSymbolAddress((void**)&qkvb, g_qkv);
    cudaGetSymbolAddress((void**)&ob, g_o);
    cudaGetSymbolAddress((void**)&gate, g_gate);
    cudaGetSymbolAddress((void**)&condb, g_cond);
    cudaGetSymbolAddress((void**)&fc, g_fc);
    cudaGetSymbolAddress((void**)&wt, g_wt);

    float* wqkv_t = wt;
    float* wo_t   = wqkv_t + WQKV_SZ;
    float* w1_t   = wo_t + WO_SZ;
    float* w2_t   = w1_t + W1_SZ;
    float* w3_t   = w2_t + W2_SZ;

    static bool attr_done = false;
    if (!attr_done) {
        cudaFuncSetAttribute(attn_kernel,
                             cudaFuncAttributeMaxDynamicSharedMemorySize, ATTN_SMEM);
        cudaFuncSetAttribute(mma_gemm<0, false>,
                             cudaFuncAttributeMaxDynamicSharedMemorySize, GEMM_SMEM);
        cudaFuncSetAttribute(mma_gemm<1, true>,
                             cudaFuncAttributeMaxDynamicSharedMemorySize, GEMM_SMEM);
        cudaFuncSetAttribute(mma_gemm<2, false>,
                             cudaFuncAttributeMaxDynamicSharedMemorySize, GEMM_SMEM);
        cudaFuncSetAttribute(mma_gemm<3, false>,
                             cudaFuncAttributeMaxDynamicSharedMemorySize, GEMM_SMEM);
        attr_done = true;
    }

    // RoPE table + weight tf32-rounding pass
    freqs_kernel<<<SEQ_T, 32>>>(fc);
    {
        int n4;
        n4 = (int)(WQKV_SZ / 4);
        cvt_kernel<<<(n4 + 255) / 256, 256>>>((const float4*)wqkv, (float4*)wqkv_t, n4);
        n4 = (int)(WO_SZ / 4);
        cvt_kernel<<<(n4 + 255) / 256, 256>>>((const float4*)wo, (float4*)wo_t, n4);
        n4 = (int)(W1_SZ / 4);
        cvt_kernel<<<(n4 + 255) / 256, 256>>>((const float4*)w1, (float4*)w1_t, n4);
        n4 = (int)(W2_SZ / 4);
        cvt_kernel<<<(n4 + 255) / 256, 256>>>((const float4*)w2, (float4*)w2_t, n4);
        n4 = (int)(W3_SZ / 4);
        cvt_kernel<<<(n4 + 255) / 256, 256>>>((const float4*)w3, (float4*)w3_t, n4);
    }

    // patch embed -> g_a  (M=8192, K=768, N=1024); cond embed -> g_cond
    mma_gemm<1, true><<<dim3(EMBED_D / 128, PATCH_M / 128), 256, GEMM_SMEM>>>(
        x, patch_w, patch_b, a, PATCH_M, EMBED_D, PATCH_K);
    mma_gemm<1, true><<<dim3(EMBED_D / 128, 1), 256, GEMM_SMEM>>>(
        cond, cond_w, cond_b, condb, BATCH, EMBED_D, EMBED_D);

    embed_ln_kernel<<<ROWS_T, 256>>>(a, condb, pos, ln_g, ln_b, h);

    const int gy = (ROWS_T + 127) / 128;  // 65

    for (int blk = 0; blk < NBLK; blk++) {
        const float* Wqkv = wqkv_t + (size_t)blk * EMBED_D * QKV_D;
        const float* Wo   = wo_t   + (size_t)blk * EMBED_D * EMBED_D;
        const float* W1   = w1_t   + (size_t)blk * EMBED_D * HID_D;
        const float* W2   = w2_t   + (size_t)blk * HID_D * EMBED_D;
        const float* W3   = w3_t   + (size_t)blk * EMBED_D * HID_D;

        rmsnorm_kernel<<<ROWS_T, 256>>>(h, anw + blk * EMBED_D, a);
        mma_gemm<0, false><<<dim3(QKV_D / 128, gy), 256, GEMM_SMEM>>>(
            a, Wqkv, nullptr, qkvb, ROWS_T, QKV_D, EMBED_D);
        attn_kernel<<<dim3(5, NHEAD, BATCH), 256, ATTN_SMEM>>>(qkvb, fc, ob);
        mma_gemm<2, false><<<dim3(EMBED_D / 128, gy), 256, GEMM_SMEM>>>(
            ob, Wo, nullptr, h, ROWS_T, EMBED_D, EMBED_D);
        rmsnorm_kernel<<<ROWS_T, 256>>>(h, fnw + blk * EMBED_D, a);
        // gate = a @ W1
        mma_gemm<0, false><<<dim3(HID_D / 128, gy), 256, GEMM_SMEM>>>(
            a, W1, nullptr, gate, ROWS_T, HID_D, EMBED_D);
        // gate = tf32(silu(gate) * (a @ W3))
        mma_gemm<3, false><<<dim3(HID_D / 128, gy), 256, GEMM_SMEM>>>(
            a, W3, nullptr, gate, ROWS_T, HID_D, EMBED_D);
        // h += gate @ W2
        mma_gemm<2, false><<<dim3(EMBED_D / 128, gy), 256, GEMM_SMEM>>>(
            gate, W2, nullptr, h, ROWS_T, EMBED_D, HID_D);
    }
}

// round 7
// speedup vs baseline: 1.6962x; 1.6962x over previous
#include <cuda_runtime.h>
#include <cuda_fp16.h>
#include <math.h>

// ---------------------------------------------------------------------------
// Problem constants
// ---------------------------------------------------------------------------
#define BATCH    32
#define SEQ_T    257                 // 1 CLS + 256 patches
#define ROWS_T   (BATCH * SEQ_T)     // 8224
#define EMBED_D  1024
#define NBLK     12
#define NHEAD    16
#define HDIM     64
#define QKV_D    3072
#define HID_D    2816
#define PATCH_M  (BATCH * 256)       // 8192
#define PATCH_K  768

// packed-weight sizes in uints (half2 = one k-pair)
#define WQKV_U   ((size_t)NBLK * (EMBED_D / 2) * QKV_D)
#define WO_U     ((size_t)NBLK * (EMBED_D / 2) * EMBED_D)
#define W1_U     ((size_t)NBLK * (EMBED_D / 2) * HID_D)
#define W2_U     ((size_t)NBLK * (HID_D / 2) * EMBED_D)
#define W3_U     W1_U
#define PW_U     ((size_t)(PATCH_K / 2) * EMBED_D)
#define CW_U     ((size_t)(EMBED_D / 2) * EMBED_D)

// ---------------------------------------------------------------------------
// Scratch (static __device__ arrays; allocation is forbidden)
// ---------------------------------------------------------------------------
__device__ __half  g_a[(size_t)ROWS_T * EMBED_D];     // normed activations (half)
__device__ float   g_qkv[(size_t)ROWS_T * QKV_D];     // qkv (fp32) / patch tmp
__device__ __half  g_o[(size_t)ROWS_T * EMBED_D];     // attention output (half)
__device__ __half  g_gate[(size_t)ROWS_T * HID_D];    // w1 out -> silu*w3 (half)
__device__ float   g_cond[(size_t)BATCH * EMBED_D];   // cond embedding (fp32)
__device__ float   g_fc[SEQ_T * 32 * 2];              // rope cos/sin
__device__ __half  g_xh[(size_t)PATCH_M * PATCH_K];   // x as half
__device__ __half  g_ch[(size_t)BATCH * EMBED_D];     // cond as half
__device__ unsigned g_wp[WQKV_U + WO_U + W1_U + W2_U + W3_U + PW_U + CW_U];

// ---------------------------------------------------------------------------
// fp16 MMA: m16n8k16, fp32 accumulate
// ---------------------------------------------------------------------------
__device__ __forceinline__ void mma_f16(float* c, const unsigned* a,
                                        const unsigned* b) {
    asm volatile(
        "mma.sync.aligned.m16n8k16.row.col.f32.f16.f16.f32 "
        "{%0,%1,%2,%3}, {%4,%5,%6,%7}, {%8,%9}, {%0,%1,%2,%3};\n"
        : "+f"(c[0]), "+f"(c[1]), "+f"(c[2]), "+f"(c[3])
        : "r"(a[0]), "r"(a[1]), "r"(a[2]), "r"(a[3]), "r"(b[0]), "r"(b[1]));
}

__device__ __forceinline__ void cp16(unsigned dst, const void* src, int sz) {
    asm volatile("cp.async.cg.shared.global [%0], [%1], 16, %2;"
                 :: "r"(dst), "l"(src), "r"(sz));
}
__device__ __forceinline__ void cp_commit() {
    asm volatile("cp.async.commit_group;" ::: "memory");
}
__device__ __forceinline__ void cp_wait0() {
    asm volatile("cp.async.wait_group 0;" ::: "memory");
}

// ---------------------------------------------------------------------------
// Conversion passes
// ---------------------------------------------------------------------------
// fp32 [K][N] -> packed half2 [K/2][N] (pair along K)
__global__ void __launch_bounds__(256)
pack_kernel(const float* __restrict__ src, unsigned* __restrict__ dst,
            int N, int total) {
    int i = blockIdx.x * 256 + threadIdx.x;
    if (i >= total) return;
    int kp = i / N, n = i - kp * N;
    float lo = src[(size_t)(2 * kp) * N + n];
    float hi = src[(size_t)(2 * kp + 1) * N + n];
    __half2 h = __floats2half2_rn(lo, hi);
    dst[i] = *(unsigned*)&h;
}

// fp32 -> half flat
__global__ void __launch_bounds__(256)
half_kernel(const float* __restrict__ src, __half* __restrict__ dst, int n) {
    int i = blockIdx.x * 256 + threadIdx.x;
    if (i < n) dst[i] = __float2half(src[i]);
}

// ---------------------------------------------------------------------------
// Block reduction (256 threads)
// ---------------------------------------------------------------------------
__device__ __forceinline__ float block_reduce_sum(float v) {
    __shared__ float sh[8];
    int lane = threadIdx.x & 31;
    int w = threadIdx.x >> 5;
#pragma unroll
    for (int o = 16; o; o >>= 1) v += __shfl_xor_sync(0xffffffffu, v, o);
    if (lane == 0) sh[w] = v;
    __syncthreads();
    if (w == 0) {
        v = (lane < 8) ? sh[lane] : 0.f;
#pragma unroll
        for (int o = 4; o; o >>= 1) v += __shfl_xor_sync(0xffffffffu, v, o);
        if (lane == 0) sh[0] = v;
    }
    __syncthreads();
    float r = sh[0];
    __syncthreads();
    return r;
}

// ---------------------------------------------------------------------------
// RoPE table:  fc[s][j][0]=cos, [1]=sin ; row 0 (CLS) is zeros (matches ref)
// ---------------------------------------------------------------------------
__global__ void freqs_kernel(float* __restrict__ fc) {
    int s = blockIdx.x;          // 0..256
    int j = threadIdx.x;         // 0..31
    float c = 0.f, sn = 0.f;
    if (s > 0) {
        int p = s - 1;
        int y = p >> 4, x = p & 15;
        int i = (j < 16) ? j : (j - 16);
        int t = (j < 16) ? y : x;
        float fr = powf(10000.0f, -(2.0f * (float)i) / 32.0f);
        float ang = (float)t * fr;
        c = cosf(ang);
        sn = sinf(ang);
    }
    fc[(s * 32 + j) * 2 + 0] = c;
    fc[(s * 32 + j) * 2 + 1] = sn;
}

// ---------------------------------------------------------------------------
// fp16 tensor-core GEMM: C[M,N] = A[M,K] @ B[K,N]
// A: half row-major [M][K]; B: packed half2 [K/2][N] (uint per k-pair).
// MODE 0: fp32 store      1: fp32 +bias    2: fp32 += C (residual)
// MODE 3: half silu-gate (reads half gate, writes half)
// MODE 4: half store
// BM=BN=128, BK=32, 256 threads (8 warps, 2x4 of 64x32 warp tiles),
// 2-stage cp.async pipeline. N%128==0, K%32==0; M guarded.
// ---------------------------------------------------------------------------
#define A_STU 20                      // uints per A-row (16 data + pad)
#define B_STU 132                     // uints per packed-B row (128 data + pad)
#define ASZ_U (128 * A_STU)           // 2560 uints
#define BSZ_U (16 * B_STU)            // 2112 uints
#define STAGE_U (ASZ_U + BSZ_U)       // 4672 uints/stage
#define GEMM_SMEM (2 * STAGE_U * 4)   // 37376 bytes

template <int MODE>
__global__ void __launch_bounds__(256)
mma_gemm(const __half* __restrict__ A, const unsigned* __restrict__ B,
         const float* __restrict__ bias, void* __restrict__ Cv,
         int M, int N, int K) {
    extern __shared__ unsigned smu[];

    const int tid = threadIdx.x;
    const int lane = tid & 31;
    const int warp = tid >> 5;
    const int gid = lane >> 2;     // 0..7
    const int ctg = lane & 3;      // 0..3
    const int mw = (warp & 1) * 64;
    const int nw = (warp >> 1) * 32;

    const int rowBase = blockIdx.y * 128;
    const int colBase = blockIdx.x * 128;

    // cp.async mapping
    const int aRow = tid >> 1;           // 0..127
    const int aChunkBase = (tid & 1) * 2;
    const int bRow0 = tid >> 5;          // 0..7
    const int bChunk = tid & 31;         // 0..31

    unsigned sbase;
    asm("{ .reg .u64 t; cvta.to.shared.u64 t, %1; cvt.u32.u64 %0, t; }"
        : "=r"(sbase) : "l"(smu));

    const bool aValid = (rowBase + aRow) < M;
    const __half* ApBase = A + (size_t)(rowBase + (aValid ? aRow : 0)) * K;

    float acc[4][4][4] = {};   // [mi][ni][frag]

    auto load_stage = [&](int stage, int k0) {
        unsigned abase = sbase + (unsigned)(stage * STAGE_U) * 4u;
#pragma unroll
        for (int j = 0; j < 2; j++) {
            int c = aChunkBase + j;          // 0..3, 8 halfs each
            cp16(abase + (unsigned)(aRow * A_STU * 4 + c * 16),
                 ApBase + k0 + c * 8, aValid ? 16 : 0);
        }
        unsigned bbase = abase + (unsigned)ASZ_U * 4u;
        int kp0 = k0 >> 1;
#pragma unroll
        for (int j = 0; j < 2; j++) {
            int r = bRow0 + 8 * j;           // 0..15
            cp16(bbase + (unsigned)(r * B_STU * 4 + bChunk * 16),
                 B + (size_t)(kp0 + r) * N + colBase + bChunk * 4, 16);
        }
        cp_commit();
    };

    load_stage(0, 0);

    int stage = 0;
    for (int k0 = 0; k0 < K; k0 += 32, stage ^= 1) {
        cp_wait0();
        __syncthreads();
        if (k0 + 32 < K) load_stage(stage ^ 1, k0 + 32);

        const unsigned* As = smu + stage * STAGE_U;
        const unsigned* Bs = As + ASZ_U;

#pragma unroll
        for (int ks = 0; ks < 2; ks++) {       // two 16-k steps
            const int au = ks * 8;             // uint col base in A
            const int bu = ks * 8;             // packed row base in B
            unsigned af[4][4], bf[4][2];
#pragma unroll
            for (int mi = 0; mi < 4; mi++) {
                const int r0 = (mw + mi * 16 + gid) * A_STU;
                const int r8 = r0 + 8 * A_STU;
                af[mi][0] = As[r0 + au + ctg];
                af[mi][1] = As[r8 + au + ctg];
                af[mi][2] = As[r0 + au + ctg + 4];
                af[mi][3] = As[r8 + au + ctg + 4];
            }
#pragma unroll
            for (int ni = 0; ni < 4; ni++) {
                const int col = nw + ni * 8 + gid;
                bf[ni][0] = Bs[(bu + ctg) * B_STU + col];
                bf[ni][1] = Bs[(bu + ctg + 4) * B_STU + col];
            }
#pragma unroll
            for (int mi = 0; mi < 4; mi++)
#pragma unroll
                for (int ni = 0; ni < 4; ni++)
                    mma_f16(acc[mi][ni], af[mi], bf[ni]);
        }
        __syncthreads();
    }

    // epilogue
#pragma unroll
    for (int mi = 0; mi < 4; mi++) {
#pragma unroll
        for (int half_ = 0; half_ < 2; half_++) {
            int row = rowBase + mw + mi * 16 + gid + half_ * 8;
            if (row >= M) continue;
#pragma unroll
            for (int ni = 0; ni < 4; ni++) {
                int col = colBase + nw + ni * 8 + 2 * ctg;
                float v0 = acc[mi][ni][half_ * 2 + 0];
                float v1 = acc[mi][ni][half_ * 2 + 1];
                if (MODE == 0 || MODE == 1 || MODE == 2) {
                    float* Cp = (float*)Cv + (size_t)row * N + col;
                    if (MODE == 1) {
                        v0 += bias[col];
                        v1 += bias[col + 1];
                    } else if (MODE == 2) {
                        float2 old = *(const float2*)Cp;
                        v0 += old.x;
                        v1 += old.y;
                    }
                    float2 out;
                    out.x = v0; out.y = v1;
                    *(float2*)Cp = out;
                } else {
                    __half* Cp = (__half*)Cv + (size_t)row * N + col;
                    if (MODE == 3) {
                        __half2 g2 = *(const __half2*)Cp;
                        float gx = __half2float(g2.x);
                        float gy = __half2float(g2.y);
                        v0 *= gx / (1.0f + __expf(-gx));
                        v1 *= gy / (1.0f + __expf(-gy));
                    }
                    *(__half2*)Cp = __floats2half2_rn(v0, v1);
                }
            }
        }
    }
}

// ---------------------------------------------------------------------------
// Embed combine (+pos) + LayerNorm -> h (d_out). One block per row.
// ---------------------------------------------------------------------------
__global__ void __launch_bounds__(256)
embed_ln_kernel(const float* __restrict__ patch, const float* __restrict__ cond,
                const float* __restrict__ pos, const float* __restrict__ g,
                const float* __restrict__ bta, float* __restrict__ h) {
    int row = blockIdx.x;
    int b = row / SEQ_T, s = row % SEQ_T;
    const float* src = (s == 0) ? (cond + (size_t)b * EMBED_D)
                                : (patch + ((size_t)b * 256 + (s - 1)) * EMBED_D);
    const float* pp = pos + (size_t)s * EMBED_D;

    float v[4];
    float sum = 0.f, sumsq = 0.f;
#pragma unroll
    for (int t = 0; t < 4; t++) {
        int idx = threadIdx.x + t * 256;
        float x = src[idx] + pp[idx];
        v[t] = x;
        sum += x;
        sumsq += x * x;
    }
    sum = block_reduce_sum(sum);
    sumsq = block_reduce_sum(sumsq);
    float mean = sum * (1.0f / EMBED_D);
    float var = sumsq * (1.0f / EMBED_D) - mean * mean;
    float inv = rsqrtf(var + 1e-6f);
#pragma unroll
    for (int t = 0; t < 4; t++) {
        int idx = threadIdx.x + t * 256;
        h[(size_t)row * EMBED_D + idx] = (v[t] - mean) * inv * g[idx] + bta[idx];
    }
}

// ---------------------------------------------------------------------------
// RMSNorm: out(half) = x * rsqrt(mean(x^2)+eps) * w. One block per row.
// ---------------------------------------------------------------------------
__global__ void __launch_bounds__(256)
rmsnorm_kernel(const float* __restrict__ x, const float* __restrict__ w,
               __half* __restrict__ out) {
    int row = blockIdx.x;
    const float* xp = x + (size_t)row * EMBED_D;
    float v[4];
    float ss = 0.f;
#pragma unroll
    for (int t = 0; t < 4; t++) {
        int idx = threadIdx.x + t * 256;
        v[t] = xp[idx];
        ss += v[t] * v[t];
    }
    ss = block_reduce_sum(ss);
    float inv = rsqrtf(ss * (1.0f / EMBED_D) + 1e-5f);
#pragma unroll
    for (int t = 0; t < 4; t++) {
        int idx = threadIdx.x + t * 256;
        out[(size_t)row * EMBED_D + idx] = __float2half(v[t] * inv * w[idx]);
    }
}

// ---------------------------------------------------------------------------
// Flash attention (fp32), RoPE fused into Q/K tile loads. Output -> half.
// grid (qtile=5, head=16, batch=32), 256 threads, 64x64 tiles.
// ---------------------------------------------------------------------------
#define ATTN_SMEM (4 * 64 * 65 * 4)

__global__ void __launch_bounds__(256)
attn_kernel(const float* __restrict__ qkv, const float* __restrict__ fc,
            __half* __restrict__ o) {
    extern __shared__ float sm[];
    float* Qs = sm;                 // [64][65]
    float* Ks = sm + 64 * 65;
    float* Vs = sm + 2 * 64 * 65;
    float* Ps = sm + 3 * 64 * 65;

    const int qt = blockIdx.x;
    const int hh = blockIdx.y;
    const int bb = blockIdx.z;
    const int tid = threadIdx.x;
    const int tx = tid & 15, ty = tid >> 4;
    const int lr = tid >> 4;         // 0..15
    const int ld = (tid & 15) << 2;  // 0..60

    const size_t bhBase = (size_t)bb * SEQ_T * QKV_D + (size_t)hh * HDIM;

#pragma unroll
    for (int i = 0; i < 4; i++) {
        int r = lr + 16 * i;
        int gq = qt * 64 + r;
        float q0 = 0, q1 = 0, q2 = 0, q3 = 0;
        if (gq < SEQ_T) {
            float4 v = *(const float4*)(qkv + bhBase + (size_t)gq * QKV_D + ld);
            int j0 = ld >> 1;
            float c0 = fc[(gq * 32 + j0) * 2 + 0], s0 = fc[(gq * 32 + j0) * 2 + 1];
            float c1 = fc[(gq * 32 + j0 + 1) * 2 + 0], s1 = fc[(gq * 32 + j0 + 1) * 2 + 1];
            q0 = v.x * c0 - v.y * s0;
            q1 = v.y * c0 + v.x * s0;
            q2 = v.z * c1 - v.w * s1;
            q3 = v.w * c1 + v.z * s1;
        }
        Qs[r * 65 + ld + 0] = q0;
        Qs[r * 65 + ld + 1] = q1;
        Qs[r * 65 + ld + 2] = q2;
        Qs[r * 65 + ld + 3] = q3;
    }

    float oacc[4][4] = {};
    float m[4], l[4];
#pragma unroll
    for (int i = 0; i < 4; i++) { m[i] = -1e30f; l[i] = 0.f; }

    const int nkt = qt + 1;
    for (int kt = 0; kt < nkt; kt++) {
#pragma unroll
        for (int i = 0; i < 4; i++) {
            int r = lr + 16 * i;
            int gk = kt * 64 + r;
            float k0 = 0, k1 = 0, k2 = 0, k3 = 0, v0 = 0, v1 = 0, v2 = 0, v3 = 0;
            if (gk < SEQ_T) {
                float4 kv = *(const float4*)(qkv + bhBase + (size_t)gk * QKV_D + 1024 + ld);
                float4 vv = *(const float4*)(qkv + bhBase + (size_t)gk * QKV_D + 2048 + ld);
                int j0 = ld >> 1;
                float c0 = fc[(gk * 32 + j0) * 2 + 0], s0 = fc[(gk * 32 + j0) * 2 + 1];
                float c1 = fc[(gk * 32 + j0 + 1) * 2 + 0], s1 = fc[(gk * 32 + j0 + 1) * 2 + 1];
                k0 = kv.x * c0 - kv.y * s0;
                k1 = kv.y * c0 + kv.x * s0;
                k2 = kv.z * c1 - kv.w * s1;
                k3 = kv.w * c1 + kv.z * s1;
                v0 = vv.x; v1 = vv.y; v2 = vv.z; v3 = vv.w;
            }
            Ks[r * 65 + ld + 0] = k0;
            Ks[r * 65 + ld + 1] = k1;
            Ks[r * 65 + ld + 2] = k2;
            Ks[r * 65 + ld + 3] = k3;
            Vs[r * 65 + ld + 0] = v0;
            Vs[r * 65 + ld + 1] = v1;
            Vs[r * 65 + ld + 2] = v2;
            Vs[r * 65 + ld + 3] = v3;
        }
        __syncthreads();

        float s[4][4] = {};
#pragma unroll 4
        for (int d = 0; d < 64; d++) {
            float ra[4], rb[4];
#pragma unroll
            for (int i = 0; i < 4; i++) ra[i] = Qs[(ty * 4 + i) * 65 + d];
#pragma unroll
            for (int j = 0; j < 4; j++) rb[j] = Ks[(tx * 4 + j) * 65 + d];
#pragma unroll
            for (int i = 0; i < 4; i++)
#pragma unroll
                for (int j = 0; j < 4; j++) s[i][j] += ra[i] * rb[j];
        }

#pragma unroll
        for (int i = 0; i < 4; i++) {
            int gq = qt * 64 + ty * 4 + i;
            float rm = -1e30f;
#pragma unroll
            for (int j = 0; j < 4; j++) {
                int gk = kt * 64 + tx * 4 + j;
                float sv = s[i][j] * 0.125f;
                if (gk > gq || gk >= SEQ_T) sv = -1e30f;
                s[i][j] = sv;
                rm = fmaxf(rm, sv);
            }
#pragma unroll
            for (int off = 8; off; off >>= 1)
                rm = fmaxf(rm, __shfl_xor_sync(0xffffffffu, rm, off));
            float newm = fmaxf(m[i], rm);
            float corr = __expf(m[i] - newm);
            float rs = 0.f;
#pragma unroll
            for (int j = 0; j < 4; j++) {
                float p = __expf(s[i][j] - newm);
                s[i][j] = p;
                rs += p;
            }
#pragma unroll
            for (int off = 8; off; off >>= 1)
                rs += __shfl_xor_sync(0xffffffffu, rs, off);
            l[i] = l[i] * corr + rs;
            m[i] = newm;
#pragma unroll
            for (int j = 0; j < 4; j++) oacc[i][j] *= corr;
        }

#pragma unroll
        for (int i = 0; i < 4; i++)
#pragma unroll
            for (int j = 0; j < 4; j++)
                Ps[(ty * 4 + i) * 65 + tx * 4 + j] = s[i][j];
        __syncthreads();

#pragma unroll 4
        for (int d = 0; d < 64; d++) {
            float ra[4], rb[4];
#pragma unroll
            for (int i = 0; i < 4; i++) ra[i] = Ps[(ty * 4 + i) * 65 + d];
#pragma unroll
            for (int j = 0; j < 4; j++) rb[j] = Vs[d * 65 + tx * 4 + j];
#pragma unroll
            for (int i = 0; i < 4; i++)
#pragma unroll
                for (int j = 0; j < 4; j++) oacc[i][j] += ra[i] * rb[j];
        }
        __syncthreads();
    }

#pragma unroll
    for (int i = 0; i < 4; i++) {
        int gq = qt * 64 + ty * 4 + i;
        if (gq >= SEQ_T) continue;
        float inv = 1.0f / l[i];
        __half* op = o + ((size_t)bb * SEQ_T + gq) * EMBED_D + hh * HDIM + tx * 4;
        __half2 r01 = __floats2half2_rn(oacc[i][0] * inv, oacc[i][1] * inv);
        __half2 r23 = __floats2half2_rn(oacc[i][2] * inv, oacc[i][3] * inv);
        *(__half2*)(op + 0) = r01;
        *(__half2*)(op + 2) = r23;
    }
}

// ---------------------------------------------------------------------------
// Launcher
// ---------------------------------------------------------------------------
extern "C" void kernel_launch(void* const* d_in, const int* in_sizes, int n_in,
                              void* d_out, int out_size) {
    const float* x       = (const float*)d_in[0];
    const float* cond    = (const float*)d_in[1];
    const float* patch_w = (const float*)d_in[2];
    const float* patch_b = (const float*)d_in[3];
    const float* ln_g    = (const float*)d_in[4];
    const float* ln_b    = (const float*)d_in[5];
    const float* pos     = (const float*)d_in[6];
    const float* cond_w  = (const float*)d_in[7];
    const float* cond_b  = (const float*)d_in[8];
    const float* wqkv    = (const float*)d_in[9];
    const float* wo      = (const float*)d_in[10];
    const float* w1      = (const float*)d_in[11];
    const float* w2      = (const float*)d_in[12];
    const float* w3      = (const float*)d_in[13];
    const float* anw     = (const float*)d_in[14];
    const float* fnw     = (const float*)d_in[15];

    float* h = (float*)d_out;

    __half *a, *ob, *gate, *xh, *ch;
    float *qkvb, *condb, *fc;
    unsigned* wp;
    cudaGetSymbolAddress((void**)&a, g_a);
    cudaGetSymbolAddress((void**)&qkvb, g_qkv);
    cudaGetSymbolAddress((void**)&ob, g_o);
    cudaGetSymbolAddress((void**)&gate, g_gate);
    cudaGetSymbolAddress((void**)&condb, g_cond);
    cudaGetSymbolAddress((void**)&fc, g_fc);
    cudaGetSymbolAddress((void**)&xh, g_xh);
    cudaGetSymbolAddress((void**)&ch, g_ch);
    cudaGetSymbolAddress((void**)&wp, g_wp);

    unsigned* wqkv_p = wp;
    unsigned* wo_p   = wqkv_p + WQKV_U;
    unsigned* w1_p   = wo_p + WO_U;
    unsigned* w2_p   = w1_p + W1_U;
    unsigned* w3_p   = w2_p + W2_U;
    unsigned* pw_p   = w3_p + W3_U;
    unsigned* cw_p   = pw_p + PW_U;

    cudaFuncSetAttribute(attn_kernel,
                         cudaFuncAttributeMaxDynamicSharedMemorySize, ATTN_SMEM);

    // prep passes
    freqs_kernel<<<SEQ_T, 32>>>(fc);
    {
        int t;
        t = (int)WQKV_U;
        pack_kernel<<<(t + 255) / 256, 256>>>(wqkv, wqkv_p, QKV_D, t);
        t = (int)WO_U;
        pack_kernel<<<(t + 255) / 256, 256>>>(wo, wo_p, EMBED_D, t);
        t = (int)W1_U;
        pack_kernel<<<(t + 255) / 256, 256>>>(w1, w1_p, HID_D, t);
        t = (int)W2_U;
        pack_kernel<<<(t + 255) / 256, 256>>>(w2, w2_p, EMBED_D, t);
        t = (int)W3_U;
        pack_kernel<<<(t + 255) / 256, 256>>>(w3, w3_p, HID_D, t);
        t = (int)PW_U;
        pack_kernel<<<(t + 255) / 256, 256>>>(patch_w, pw_p, EMBED_D, t);
        t = (int)CW_U;
        pack_kernel<<<(t + 255) / 256, 256>>>(cond_w, cw_p, EMBED_D, t);
        t = PATCH_M * PATCH_K;
        half_kernel<<<(t + 255) / 256, 256>>>(x, xh, t);
        t = BATCH * EMBED_D;
        half_kernel<<<(t + 255) / 256, 256>>>(cond, ch, t);
    }

    // patch embed -> g_qkv (fp32 tmp, [8192,1024]); cond embed -> g_cond
    mma_gemm<1><<<dim3(EMBED_D / 128, PATCH_M / 128), 256, GEMM_SMEM>>>(
        xh, pw_p, patch_b, qkvb, PATCH_M, EMBED_D, PATCH_K);
    mma_gemm<1><<<dim3(EMBED_D / 128, 1), 256, GEMM_SMEM>>>(
        ch, cw_p, cond_b, condb, BATCH, EMBED_D, EMBED_D);

    embed_ln_kernel<<<ROWS_T, 256>>>(qkvb, condb, pos, ln_g, ln_b, h);

    const int gy = (ROWS_T + 127) / 128;  // 65

    for (int blk = 0; blk < NBLK; blk++) {
        const unsigned* Wqkv = wqkv_p + (size_t)blk * (EMBED_D / 2) * QKV_D;
        const unsigned* Wo   = wo_p   + (size_t)blk * (EMBED_D / 2) * EMBED_D;
        const unsigned* W1   = w1_p   + (size_t)blk * (EMBED_D / 2) * HID_D;
        const unsigned* W2   = w2_p   + (size_t)blk * (HID_D / 2) * EMBED_D;
        const unsigned* W3   = w3_p   + (size_t)blk * (EMBED_D / 2) * HID_D;

        rmsnorm_kernel<<<ROWS_T, 256>>>(h, anw + blk * EMBED_D, a);
        mma_gemm<0><<<dim3(QKV_D / 128, gy), 256, GEMM_SMEM>>>(
            a, Wqkv, nullptr, qkvb, ROWS_T, QKV_D, EMBED_D);
        attn_kernel<<<dim3(5, NHEAD, BATCH), 256, ATTN_SMEM>>>(qkvb, fc, ob);
        mma_gemm<2><<<dim3(EMBED_D / 128, gy), 256, GEMM_SMEM>>>(
            ob, Wo, nullptr, h, ROWS_T, EMBED_D, EMBED_D);
        rmsnorm_kernel<<<ROWS_T, 256>>>(h, fnw + blk * EMBED_D, a);
        // gate(half) = a @ W1
        mma_gemm<4><<<dim3(HID_D / 128, gy), 256, GEMM_SMEM>>>(
            a, W1, nullptr, gate, ROWS_T, HID_D, EMBED_D);
        // gate = silu(gate) * (a @ W3)
        mma_gemm<3><<<dim3(HID_D / 128, gy), 256, GEMM_SMEM>>>(
            a, W3, nullptr, gate, ROWS_T, HID_D, EMBED_D);
        // h += gate @ W2
        mma_gemm<2><<<dim3(EMBED_D / 128, gy), 256, GEMM_SMEM>>>(
            gate, W2, nullptr, h, ROWS_T, EMBED_D, HID_D);
    }
}